// round 5
// baseline (speedup 1.0000x reference)
#include <cuda_runtime.h>
#include <cuda_bf16.h>

// Problem constants (fixed by the reference)
#define N_ATOMS   2048
#define N_RBF     16
#define N_HIDDEN  32
// centers c_k = k/3 (linspace(0,5,16)), gamma = 9.
// exp(-9 (d-c_k)^2) = exp2( -9L d^2 + (6L k) d - L k^2 ),  L = log2(e)
#define LOG2E     (1.4426950408889634f)
#define NEG9L     (-12.98425537f)     // -9*log2(e)

#define JSPLIT          2                       // warps per atom (j-range split)
#define ATOMS_PER_BLOCK 4
#define WARPS_PER_BLOCK (ATOMS_PER_BLOCK * JSPLIT)   // 8
#define BLOCK           (32 * WARPS_PER_BLOCK)       // 256 threads
#define NBLOCKS         (N_ATOMS / ATOMS_PER_BLOCK)  // 512 blocks
#define JLEN            (N_ATOMS / JSPLIT)           // 1024 j's per warp

// device scratch (no runtime alloc allowed); zero-initialized at module load
__device__ float        g_bsum[NBLOCKS];
__device__ unsigned int g_count;

__device__ __forceinline__ float fast_ex2(float x) {
    float r; asm("ex2.approx.ftz.f32 %0, %1;" : "=f"(r) : "f"(x)); return r;
}
__device__ __forceinline__ float fast_rsq(float x) {
    float r; asm("rsqrt.approx.ftz.f32 %0, %1;" : "=f"(r) : "f"(x)); return r;
}
__device__ __forceinline__ float fast_rcp(float x) {
    float r; asm("rcp.approx.ftz.f32 %0, %1;" : "=f"(r) : "f"(x)); return r;
}

// 16-center Gaussian RBF for one compacted pair: input d^2.
// E_k = (-9L d^2 - L k^2) + d * (6L k); per k: FADD + FMA + EX2 + FADD.
__device__ __forceinline__ void accum_rbf_d2(float d2, float feat[N_RBF]) {
    const float d = d2 * fast_rsq(d2);     // sqrt(d2)
    const float a = NEG9L * d2;
#pragma unroll
    for (int k = 0; k < N_RBF; k++) {
        const float c1 = 6.0f * LOG2E * (float)k;
        const float c0 = -LOG2E * (float)(k * k);
        feat[k] += fast_ex2(fmaf(d, c1, a + c0));
    }
}

__global__ void __launch_bounds__(BLOCK) fused_kernel(
    const float* __restrict__ pos,
    const int*   __restrict__ cs,
    const float* __restrict__ emb,
    const float* __restrict__ W1,   // [48][32] row-major
    const float* __restrict__ b1,   // [32]
    const float* __restrict__ W2,   // [32]
    const float* __restrict__ b2,   // [1]
    float*       __restrict__ out)
{
    __shared__ float sbuf[WARPS_PER_BLOCK][64];       // ring buffers (d^2)
    __shared__ float sfeat[WARPS_PER_BLOCK][N_RBF];   // per-warp partial feats
    __shared__ float sred[ATOMS_PER_BLOCK];
    __shared__ float sfin[BLOCK];
    __shared__ bool  isLast;

    const int tid  = threadIdx.x;
    const int wid  = tid >> 5;
    const int lane = tid & 31;

    const int atom_local = wid >> 1;          // wid / JSPLIT
    const int half       = wid & (JSPLIT - 1);
    const int i = blockIdx.x * ATOMS_PER_BLOCK + atom_local;

    const float xi = __ldg(&pos[3 * i + 0]);
    const float yi = __ldg(&pos[3 * i + 1]);
    const float zi = __ldg(&pos[3 * i + 2]);

    float feat[N_RBF];
#pragma unroll
    for (int k = 0; k < N_RBF; k++) feat[k] = 0.0f;

    float* buf = sbuf[wid];
    int base = 0, cnt = 0;                     // ring: occupied = [base, cnt)

    // ---- pairwise pass over this warp's j-half: compaction + dense exps ----
    const int jbeg = half * JLEN;
    for (int j0 = jbeg; j0 < jbeg + JLEN; j0 += 32) {
        const int j = j0 + lane;
        const float dx = xi - __ldg(&pos[3 * j + 0]);
        const float dy = yi - __ldg(&pos[3 * j + 1]);
        const float dz = zi - __ldg(&pos[3 * j + 2]);
        const float d2 = fmaf(dx, dx, fmaf(dy, dy, dz * dz));
        const bool pass = (d2 > 0.0f) && (d2 < 25.0f);
        const unsigned m = __ballot_sync(0xFFFFFFFFu, pass);
        if (pass) {
            const int rank = __popc(m & ((1u << lane) - 1u));
            buf[(cnt + rank) & 63] = d2;       // ring write, no carry copy
        }
        cnt += __popc(m);
        __syncwarp();                           // writes -> visible for flush
        if (cnt - base >= 32) {                 // flush one dense batch
            accum_rbf_d2(buf[(base + lane) & 63], feat);
            base += 32;
            __syncwarp();                       // reads done before next writes
        }
    }
    // tail: inactive lanes get huge d^2 -> exp2(-huge) == 0
    if (cnt > base) {
        const float d2b = (lane < cnt - base) ? buf[(base + lane) & 63] : 4.0e9f;
        accum_rbf_d2(d2b, feat);
    }

    // ---- warp-reduce partial feats, publish to smem ----
#pragma unroll
    for (int k = 0; k < N_RBF; k++) {
        float v = feat[k];
        v += __shfl_xor_sync(0xFFFFFFFFu, v, 16);
        v += __shfl_xor_sync(0xFFFFFFFFu, v, 8);
        v += __shfl_xor_sync(0xFFFFFFFFu, v, 4);
        v += __shfl_xor_sync(0xFFFFFFFFu, v, 2);
        v += __shfl_xor_sync(0xFFFFFFFFu, v, 1);
        feat[k] = v;
    }
    if (lane == 0) {
#pragma unroll
        for (int k = 0; k < N_RBF; k++) sfeat[wid][k] = feat[k];
    }
    __syncthreads();

    // ---- MLP: warp a (a < ATOMS_PER_BLOCK) handles atom a; lane = hidden ----
    if (wid < ATOMS_PER_BLOCK) {
        const int csi = (__ldg(cs) < 0) ? 0 : 1;
        float h = __ldg(&b1[lane]);
#pragma unroll
        for (int k = 0; k < N_RBF; k++) {
            const float fk = sfeat[JSPLIT * wid][k] + sfeat[JSPLIT * wid + 1][k];
            h = fmaf(fk, __ldg(&W1[k * N_HIDDEN + lane]), h);
        }
#pragma unroll
        for (int mrow = 0; mrow < N_HIDDEN; mrow++)
            h = fmaf(__ldg(&emb[csi * N_HIDDEN + mrow]),
                     __ldg(&W1[(N_RBF + mrow) * N_HIDDEN + lane]), h);

        // silu(h) = h / (1 + e^{-h})
        const float s = h * fast_rcp(1.0f + fast_ex2(-LOG2E * h));
        float e = s * __ldg(&W2[lane]);
        e += __shfl_xor_sync(0xFFFFFFFFu, e, 16);
        e += __shfl_xor_sync(0xFFFFFFFFu, e, 8);
        e += __shfl_xor_sync(0xFFFFFFFFu, e, 4);
        e += __shfl_xor_sync(0xFFFFFFFFu, e, 2);
        e += __shfl_xor_sync(0xFFFFFFFFu, e, 1);
        if (lane == 0) sred[wid] = e + __ldg(b2);
    }
    __syncthreads();

    // ---- publish block partial; last block reduces deterministically ----
    if (tid == 0) {
        float acc = 0.0f;
#pragma unroll
        for (int a = 0; a < ATOMS_PER_BLOCK; a++) acc += sred[a];
        g_bsum[blockIdx.x] = acc;
        __threadfence();
        const unsigned v = atomicAdd(&g_count, 1u);
        isLast = (v == (unsigned)(NBLOCKS - 1));
    }
    __syncthreads();

    if (isLast) {
        float acc = 0.0f;
#pragma unroll
        for (int r = 0; r < NBLOCKS / BLOCK; r++)
            acc += __ldcg(&g_bsum[r * BLOCK + tid]);
        sfin[tid] = acc;
        __syncthreads();
#pragma unroll
        for (int s = BLOCK / 2; s > 0; s >>= 1) {
            if (tid < s) sfin[tid] += sfin[tid + s];
            __syncthreads();
        }
        if (tid == 0) {
            out[0] = sfin[0];
            g_count = 0;                // reset for next graph replay
        }
    }
}

extern "C" void kernel_launch(void* const* d_in, const int* in_sizes, int n_in,
                              void* d_out, int out_size) {
    const float* pos = (const float*)d_in[0];
    const int*   cs  = (const int*)  d_in[1];
    const float* emb = (const float*)d_in[2];
    const float* W1  = (const float*)d_in[3];
    const float* b1  = (const float*)d_in[4];
    const float* W2  = (const float*)d_in[5];
    const float* b2  = (const float*)d_in[6];
    float* out = (float*)d_out;

    fused_kernel<<<NBLOCKS, BLOCK>>>(pos, cs, emb, W1, b1, W2, b2, out);
}

// round 6
// speedup vs baseline: 1.1395x; 1.1395x over previous
#include <cuda_runtime.h>
#include <cuda_bf16.h>

// Problem constants (fixed by the reference)
#define N_ATOMS   2048
#define N_RBF     16
#define N_HIDDEN  32
// centers c_k = k/3 (linspace(0,5,16)), gamma = 9.
// exp(-9 (d-c_k)^2) = exp2( -9L d^2 + (6L k) d - L k^2 ),  L = log2(e)
#define LOG2E     (1.4426950408889634f)
#define NEG9L     (-12.98425537f)     // -9*log2(e)

#define ATOMS_PER_BLOCK 4
#define WARPS_PER_BLOCK 8            // (pair p in {0,1}) x (quarter q in {0..3})
#define BLOCK           256
#define NBLOCKS         (N_ATOMS / ATOMS_PER_BLOCK)   // 512
#define JQ              (N_ATOMS / 4)                  // 512 j's per quarter
#define NCHUNK          (JQ / 32)                      // 16 chunks

// device scratch (no runtime alloc allowed); zero-initialized at module load
__device__ float        g_bsum[NBLOCKS];
__device__ unsigned int g_count;

__device__ __forceinline__ float fast_ex2(float x) {
    float r; asm("ex2.approx.ftz.f32 %0, %1;" : "=f"(r) : "f"(x)); return r;
}
__device__ __forceinline__ float fast_rsq(float x) {
    float r; asm("rsqrt.approx.ftz.f32 %0, %1;" : "=f"(r) : "f"(x)); return r;
}
__device__ __forceinline__ float fast_rcp(float x) {
    float r; asm("rcp.approx.ftz.f32 %0, %1;" : "=f"(r) : "f"(x)); return r;
}

// 16-center Gaussian RBF for one pair (input d^2).
// E_k = (-9L d^2 - L k^2) + d * (6L k); per k: FADD + FMA + EX2 + FADD.
__device__ __forceinline__ void accum_rbf_d2(float d2, float feat[N_RBF]) {
    const float d = d2 * fast_rsq(d2);     // sqrt(d2)
    const float a = NEG9L * d2;
#pragma unroll
    for (int k = 0; k < N_RBF; k++) {
        const float c1 = 6.0f * LOG2E * (float)k;
        const float c0 = -LOG2E * (float)(k * k);
        feat[k] += fast_ex2(fmaf(d, c1, a + c0));
    }
}

__global__ void __launch_bounds__(BLOCK, 4) fused_kernel(
    const float* __restrict__ pos,
    const int*   __restrict__ cs,
    const float* __restrict__ emb,
    const float* __restrict__ W1,   // [48][32] row-major
    const float* __restrict__ b1,   // [32]
    const float* __restrict__ W2,   // [32]
    const float* __restrict__ b2,   // [1]
    float*       __restrict__ out)
{
    // full-size compaction buffers: warp w, atom sel s -> 512 slots (no overflow)
    __shared__ float sbuf[WARPS_PER_BLOCK][2][JQ];              // 32 KB
    __shared__ float sfeat[ATOMS_PER_BLOCK][4][N_RBF];          // 1 KB
    __shared__ float sred[ATOMS_PER_BLOCK];
    __shared__ float sfin[BLOCK];
    __shared__ bool  isLast;

    const int tid  = threadIdx.x;
    const int wid  = tid >> 5;
    const int lane = tid & 31;
    const unsigned lmask = (1u << lane) - 1u;

    const int q = wid >> 1;            // j-quarter 0..3
    const int p = wid & 1;             // atom pair 0..1
    const int i0 = blockIdx.x * ATOMS_PER_BLOCK + 2 * p;
    const int i1 = i0 + 1;

    const float x0 = __ldg(&pos[3 * i0 + 0]);
    const float y0 = __ldg(&pos[3 * i0 + 1]);
    const float z0 = __ldg(&pos[3 * i0 + 2]);
    const float x1 = __ldg(&pos[3 * i1 + 0]);
    const float y1 = __ldg(&pos[3 * i1 + 1]);
    const float z1 = __ldg(&pos[3 * i1 + 2]);

    float fA[N_RBF], fB[N_RBF];
#pragma unroll
    for (int k = 0; k < N_RBF; k++) { fA[k] = 0.0f; fB[k] = 0.0f; }

    float* bufA = sbuf[wid][0];
    float* bufB = sbuf[wid][1];
    int cA = 0, cB = 0;

    // ---- dist pass over this warp's j-quarter: no syncs, no flushes ----
    const int jbeg = q * JQ;
#pragma unroll 4
    for (int c = 0; c < NCHUNK; c++) {
        const int j = jbeg + c * 32 + lane;
        const float px = __ldg(&pos[3 * j + 0]);
        const float py = __ldg(&pos[3 * j + 1]);
        const float pz = __ldg(&pos[3 * j + 2]);

        const float dxA = x0 - px, dyA = y0 - py, dzA = z0 - pz;
        const float dxB = x1 - px, dyB = y1 - py, dzB = z1 - pz;
        const float d2A = fmaf(dxA, dxA, fmaf(dyA, dyA, dzA * dzA));
        const float d2B = fmaf(dxB, dxB, fmaf(dyB, dyB, dzB * dzB));

        const bool pA = (d2A > 0.0f) && (d2A < 25.0f);
        const bool pB = (d2B > 0.0f) && (d2B < 25.0f);
        const unsigned mA = __ballot_sync(0xFFFFFFFFu, pA);
        const unsigned mB = __ballot_sync(0xFFFFFFFFu, pB);
        if (pA) bufA[cA + __popc(mA & lmask)] = d2A;
        if (pB) bufB[cB + __popc(mB & lmask)] = d2B;
        cA += __popc(mA);
        cB += __popc(mB);
    }
    __syncwarp();

    // ---- dense exp phase: batches of 32 compacted pairs ----
    for (int b = 0; b < cA; b += 32) {
        const float d2 = (b + lane < cA) ? bufA[b + lane] : 4.0e9f;
        accum_rbf_d2(d2, fA);
    }
    for (int b = 0; b < cB; b += 32) {
        const float d2 = (b + lane < cB) ? bufB[b + lane] : 4.0e9f;
        accum_rbf_d2(d2, fB);
    }

    // ---- warp-reduce each k; lane k keeps the two totals ----
    float vA = 0.0f, vB = 0.0f;
#pragma unroll
    for (int k = 0; k < N_RBF; k++) {
        float a = fA[k], b = fB[k];
        a += __shfl_xor_sync(0xFFFFFFFFu, a, 16);
        b += __shfl_xor_sync(0xFFFFFFFFu, b, 16);
        a += __shfl_xor_sync(0xFFFFFFFFu, a, 8);
        b += __shfl_xor_sync(0xFFFFFFFFu, b, 8);
        a += __shfl_xor_sync(0xFFFFFFFFu, a, 4);
        b += __shfl_xor_sync(0xFFFFFFFFu, b, 4);
        a += __shfl_xor_sync(0xFFFFFFFFu, a, 2);
        b += __shfl_xor_sync(0xFFFFFFFFu, b, 2);
        a += __shfl_xor_sync(0xFFFFFFFFu, a, 1);
        b += __shfl_xor_sync(0xFFFFFFFFu, b, 1);
        if (lane == k) { vA = a; vB = b; }
    }
    if (lane < N_RBF) {
        sfeat[2 * p + 0][q][lane] = vA;
        sfeat[2 * p + 1][q][lane] = vB;
    }
    __syncthreads();

    // ---- MLP: warp a (a < 4) handles atom a; lane = hidden unit ----
    if (wid < ATOMS_PER_BLOCK) {
        const int csi = (__ldg(cs) < 0) ? 0 : 1;
        float h = __ldg(&b1[lane]);
#pragma unroll
        for (int k = 0; k < N_RBF; k++) {
            const float fk = (sfeat[wid][0][k] + sfeat[wid][1][k])
                           + (sfeat[wid][2][k] + sfeat[wid][3][k]);
            h = fmaf(fk, __ldg(&W1[k * N_HIDDEN + lane]), h);
        }
#pragma unroll
        for (int m = 0; m < N_HIDDEN; m++)
            h = fmaf(__ldg(&emb[csi * N_HIDDEN + m]),
                     __ldg(&W1[(N_RBF + m) * N_HIDDEN + lane]), h);

        // silu(h) = h / (1 + e^{-h})
        const float s = h * fast_rcp(1.0f + fast_ex2(-LOG2E * h));
        float e = s * __ldg(&W2[lane]);
        e += __shfl_xor_sync(0xFFFFFFFFu, e, 16);
        e += __shfl_xor_sync(0xFFFFFFFFu, e, 8);
        e += __shfl_xor_sync(0xFFFFFFFFu, e, 4);
        e += __shfl_xor_sync(0xFFFFFFFFu, e, 2);
        e += __shfl_xor_sync(0xFFFFFFFFu, e, 1);
        if (lane == 0) sred[wid] = e + __ldg(b2);
    }
    __syncthreads();

    // ---- publish block partial; last block reduces deterministically ----
    if (tid == 0) {
        float acc = (sred[0] + sred[1]) + (sred[2] + sred[3]);
        g_bsum[blockIdx.x] = acc;
        __threadfence();
        const unsigned v = atomicAdd(&g_count, 1u);
        isLast = (v == (unsigned)(NBLOCKS - 1));
    }
    __syncthreads();

    if (isLast) {
        float acc = 0.0f;
#pragma unroll
        for (int r = 0; r < NBLOCKS / BLOCK; r++)
            acc += __ldcg(&g_bsum[r * BLOCK + tid]);
        sfin[tid] = acc;
        __syncthreads();
#pragma unroll
        for (int s = BLOCK / 2; s > 0; s >>= 1) {
            if (tid < s) sfin[tid] += sfin[tid + s];
            __syncthreads();
        }
        if (tid == 0) {
            out[0] = sfin[0];
            g_count = 0;                // reset for next graph replay
        }
    }
}

extern "C" void kernel_launch(void* const* d_in, const int* in_sizes, int n_in,
                              void* d_out, int out_size) {
    const float* pos = (const float*)d_in[0];
    const int*   cs  = (const int*)  d_in[1];
    const float* emb = (const float*)d_in[2];
    const float* W1  = (const float*)d_in[3];
    const float* b1  = (const float*)d_in[4];
    const float* W2  = (const float*)d_in[5];
    const float* b2  = (const float*)d_in[6];
    float* out = (float*)d_out;

    fused_kernel<<<NBLOCKS, BLOCK>>>(pos, cs, emb, W1, b1, W2, b2, out);
}

// round 8
// speedup vs baseline: 1.3310x; 1.1681x over previous
#include <cuda_runtime.h>
#include <cuda_bf16.h>

// Problem constants (fixed by the reference)
#define N_ATOMS   2048
#define N_RBF     16
#define N_HIDDEN  32
// centers c_k = k/3 (linspace(0,5,16)), gamma = 9. With m = 3d:
// g_k = e^{-(m-k)^2} = P * rho^k * T[k*-k],
//   k* = round(m), f = m-k*, P = exp2(-L f (f+2k*)), rho = exp2(2 L f),
//   T[j] = e^{-j^2}  (j in [-15,15]; zero outside)
#define LOG2E     (1.4426950408889634f)

#define ATOMS_PER_BLOCK 2
#define WARPS_PER_BLOCK 8              // each warp: one j-slice, both atoms
#define BLOCK           256
#define NBLOCKS         (N_ATOMS / ATOMS_PER_BLOCK)   // 1024
#define JSL             (N_ATOMS / WARPS_PER_BLOCK)   // 256 j's per slice
#define NCHUNK          (JSL / 32)                    // 8 chunks
#define PAD_D2          (177.78f)      // m=40 -> T indices in zero region

// device scratch (no runtime alloc allowed); zero-initialized at module load
__device__ float        g_bsum[NBLOCKS];
__device__ unsigned int g_count;

__device__ __forceinline__ float fast_ex2(float x) {
    float r; asm("ex2.approx.ftz.f32 %0, %1;" : "=f"(r) : "f"(x)); return r;
}
__device__ __forceinline__ float fast_rsq(float x) {
    float r; asm("rsqrt.approx.ftz.f32 %0, %1;" : "=f"(r) : "f"(x)); return r;
}
__device__ __forceinline__ float fast_rcp(float x) {
    float r; asm("rcp.approx.ftz.f32 %0, %1;" : "=f"(r) : "f"(x)); return r;
}

// Table-factored 16-center RBF accumulation for one pair (input d^2).
// feat[k] += P * rho^k * T[k*+15-k]; only 2 EX2 + 1 RSQ of MUFU work.
__device__ __forceinline__ void accum_rbf_tbl(float d2, const float* __restrict__ sT,
                                              float* __restrict__ feat) {
    const float d  = d2 * fast_rsq(d2);           // sqrt(d2)
    const float m  = 3.0f * d;                    // scaled distance in [0,15]
    const int   ki = __float2int_rn(m);           // nearest center index
    const float kf = (float)ki;
    const float f  = m - kf;                      // |f| <= 0.5
    const float s2 = -LOG2E * f;
    const float s1 = fmaf(2.0f, kf, f);           // f + 2k*
    const float P  = fast_ex2(s1 * s2);           // exp2(-L f (f+2k*))
    const float ri = fast_ex2(-2.0f * s2);        // exp2(2 L f) = rho
    const float r2 = ri * ri;
    const float* Tb = sT + ki + 15;               // T[ki+15-k] via imm offsets
    float t0 = P;                                  // rho^0 chain (even k)
    float t1 = P * ri;                             // rho^1 chain (odd k)
#pragma unroll
    for (int k = 0; k < N_RBF; k += 2) {
        feat[k]     = fmaf(t0, Tb[-k],     feat[k]);
        feat[k + 1] = fmaf(t1, Tb[-(k+1)], feat[k + 1]);
        t0 *= r2;
        t1 *= r2;
    }
}

__global__ void __launch_bounds__(BLOCK, 4) fused_kernel(
    const float* __restrict__ pos,
    const int*   __restrict__ cs,
    const float* __restrict__ emb,
    const float* __restrict__ W1,   // [48][32] row-major
    const float* __restrict__ b1,   // [32]
    const float* __restrict__ W2,   // [32]
    const float* __restrict__ b2,   // [1]
    float*       __restrict__ out)
{
    __shared__ float sbuf[WARPS_PER_BLOCK][2][JSL];     // 16 KB compaction
    __shared__ float sT[64];                             // e^{-j^2} table
    __shared__ float sfeat[2][N_RBF][9];                 // [atom][k][slice] pad 9
    __shared__ float sred[2];
    __shared__ float sfin[BLOCK];
    __shared__ bool  isLast;

    const int tid  = threadIdx.x;
    const int wid  = tid >> 5;
    const int lane = tid & 31;
    const unsigned lmask = (1u << lane) - 1u;

    // Build e^{-j^2} table: index t -> j = t-15; zero for t > 30.
    if (tid < 64) {
        const int j = tid - 15;
        sT[tid] = (tid <= 30) ? fast_ex2(-LOG2E * (float)(j * j)) : 0.0f;
    }

    const int i0 = blockIdx.x * ATOMS_PER_BLOCK;
    const int i1 = i0 + 1;
    const float x0 = __ldg(&pos[3 * i0 + 0]);
    const float y0 = __ldg(&pos[3 * i0 + 1]);
    const float z0 = __ldg(&pos[3 * i0 + 2]);
    const float x1 = __ldg(&pos[3 * i1 + 0]);
    const float y1 = __ldg(&pos[3 * i1 + 1]);
    const float z1 = __ldg(&pos[3 * i1 + 2]);

    float feat[32];                   // [0..15] atom0, [16..31] atom1
#pragma unroll
    for (int k = 0; k < 32; k++) feat[k] = 0.0f;

    float* bufA = sbuf[wid][0];
    float* bufB = sbuf[wid][1];
    int cA = 0, cB = 0;

    __syncthreads();                  // sT ready

    // ---- dist pass over this warp's 256-j slice: no syncs, no flushes ----
    const int jbeg = wid * JSL;
#pragma unroll 4
    for (int c = 0; c < NCHUNK; c++) {
        const int j = jbeg + c * 32 + lane;
        const float px = __ldg(&pos[3 * j + 0]);
        const float py = __ldg(&pos[3 * j + 1]);
        const float pz = __ldg(&pos[3 * j + 2]);

        const float dxA = x0 - px, dyA = y0 - py, dzA = z0 - pz;
        const float dxB = x1 - px, dyB = y1 - py, dzB = z1 - pz;
        const float d2A = fmaf(dxA, dxA, fmaf(dyA, dyA, dzA * dzA));
        const float d2B = fmaf(dxB, dxB, fmaf(dyB, dyB, dzB * dzB));

        const bool pA = (d2A > 0.0f) && (d2A < 25.0f);
        const bool pB = (d2B > 0.0f) && (d2B < 25.0f);
        const unsigned mA = __ballot_sync(0xFFFFFFFFu, pA);
        const unsigned mB = __ballot_sync(0xFFFFFFFFu, pB);
        if (pA) bufA[cA + __popc(mA & lmask)] = d2A;
        if (pB) bufB[cB + __popc(mB & lmask)] = d2B;
        cA += __popc(mA);
        cB += __popc(mB);
    }
    __syncwarp();

    // ---- dense exp phase: batches of 32 compacted pairs ----
    for (int b = 0; b < cA; b += 32) {
        const float d2 = (b + lane < cA) ? bufA[b + lane] : PAD_D2;
        accum_rbf_tbl(d2, sT, feat);
    }
    for (int b = 0; b < cB; b += 32) {
        const float d2 = (b + lane < cB) ? bufB[b + lane] : PAD_D2;
        accum_rbf_tbl(d2, sT, feat + N_RBF);
    }

    // ---- index-folding exchange reduce: 32 sums over 32 lanes.
    // After the fold, lane l holds the total for value-index l.
#pragma unroll
    for (int bit = 16; bit >= 1; bit >>= 1) {
        const bool up = (lane & bit) != 0;
#pragma unroll
        for (int j = 0; j < bit; j++) {
            const float lo = feat[j], hi = feat[j + bit];
            const float send = up ? lo : hi;
            const float recv = __shfl_xor_sync(0xFFFFFFFFu, send, bit);
            feat[j] = (up ? hi : lo) + recv;
        }
    }
    if (lane < N_RBF) sfeat[0][lane][wid] = feat[0];
    else              sfeat[1][lane - N_RBF][wid] = feat[0];
    __syncthreads();

    // ---- MLP: warp a (a < 2) handles atom a; lane = hidden unit ----
    if (wid < ATOMS_PER_BLOCK) {
        const int csi = (__ldg(cs) < 0) ? 0 : 1;
        float h = __ldg(&b1[lane]);
#pragma unroll
        for (int k = 0; k < N_RBF; k++) {
            float fk = 0.0f;
#pragma unroll
            for (int s = 0; s < WARPS_PER_BLOCK; s++) fk += sfeat[wid][k][s];
            h = fmaf(fk, __ldg(&W1[k * N_HIDDEN + lane]), h);
        }
#pragma unroll
        for (int m = 0; m < N_HIDDEN; m++)
            h = fmaf(__ldg(&emb[csi * N_HIDDEN + m]),
                     __ldg(&W1[(N_RBF + m) * N_HIDDEN + lane]), h);

        // silu(h) = h / (1 + e^{-h})
        const float s = h * fast_rcp(1.0f + fast_ex2(-LOG2E * h));
        float e = s * __ldg(&W2[lane]);
        e += __shfl_xor_sync(0xFFFFFFFFu, e, 16);
        e += __shfl_xor_sync(0xFFFFFFFFu, e, 8);
        e += __shfl_xor_sync(0xFFFFFFFFu, e, 4);
        e += __shfl_xor_sync(0xFFFFFFFFu, e, 2);
        e += __shfl_xor_sync(0xFFFFFFFFu, e, 1);
        if (lane == 0) sred[wid] = e + __ldg(b2);
    }
    __syncthreads();

    // ---- publish block partial; last block reduces deterministically ----
    if (tid == 0) {
        g_bsum[blockIdx.x] = sred[0] + sred[1];
        __threadfence();
        const unsigned v = atomicAdd(&g_count, 1u);
        isLast = (v == (unsigned)(NBLOCKS - 1));
    }
    __syncthreads();

    if (isLast) {
        float acc = 0.0f;
#pragma unroll
        for (int r = 0; r < NBLOCKS / BLOCK; r++)
            acc += __ldcg(&g_bsum[r * BLOCK + tid]);
        sfin[tid] = acc;
        __syncthreads();
#pragma unroll
        for (int s = BLOCK / 2; s > 0; s >>= 1) {
            if (tid < s) sfin[tid] += sfin[tid + s];
            __syncthreads();
        }
        if (tid == 0) {
            out[0] = sfin[0];
            g_count = 0;                // reset for next graph replay
        }
    }
}

extern "C" void kernel_launch(void* const* d_in, const int* in_sizes, int n_in,
                              void* d_out, int out_size) {
    const float* pos = (const float*)d_in[0];
    const int*   cs  = (const int*)  d_in[1];
    const float* emb = (const float*)d_in[2];
    const float* W1  = (const float*)d_in[3];
    const float* b1  = (const float*)d_in[4];
    const float* W2  = (const float*)d_in[5];
    const float* b2  = (const float*)d_in[6];
    float* out = (float*)d_out;

    fused_kernel<<<NBLOCKS, BLOCK>>>(pos, cs, emb, W1, b1, W2, b2, out);
}